// round 4
// baseline (speedup 1.0000x reference)
#include <cuda_runtime.h>
#include <cstdint>

namespace {
constexpr int B = 32, S = 1024, DM = 128, DI = 256, DS = 16, DTR = 8, NL = 4;
constexpr int MTOT = B * S;
}

// ---------------- scratch (device globals; no allocation allowed) -------------
__device__ float g_h[MTOT * DM];        // residual stream
__device__ float g_hn[MTOT * DM];       // rmsnormed
__device__ float g_xz[MTOT * 2 * DI];   // in_proj out: [xb | z]
__device__ float g_xc[MTOT * DI];       // conv+silu out (u)
__device__ float g_dbc[MTOT * 40];      // x_proj out: [dt(8) | B(16) | C(16)]
__device__ float g_delta[MTOT * DI];
__device__ float g_y[MTOT * DI];        // gated scan output

__device__ __forceinline__ float siluf(float x) { return x / (1.f + __expf(-x)); }

// ---------------- f32x2 packed-FMA helpers (Blackwell FFMA2) ------------------
__device__ __forceinline__ unsigned long long pk2(float x, float y) {
    unsigned long long r;
    asm("mov.b64 %0, {%1, %2};" : "=l"(r) : "f"(x), "f"(y));
    return r;
}
__device__ __forceinline__ unsigned long long pkdup(float x) {
    unsigned long long r;
    asm("mov.b64 %0, {%1, %1};" : "=l"(r) : "f"(x));
    return r;
}
__device__ __forceinline__ void fma2(unsigned long long& c, unsigned long long a,
                                     unsigned long long b) {
    asm("fma.rn.f32x2 %0, %1, %2, %0;" : "+l"(c) : "l"(a), "l"(b));
}
__device__ __forceinline__ void upk2(unsigned long long c, float& lo, float& hi) {
    asm("mov.b64 {%0, %1}, %2;" : "=f"(lo), "=f"(hi) : "l"(c));
}

// ---------------- GEMM: C[M,N] = A[M,K] @ W[N,K]^T via FFMA2 ------------------
// BM=128, BN=128, BK=16, 256 threads. Thread (tx,ty): 8 M-rows (4 pairs) x
// 8 N-cols (two groups of 4: tx*4 and 64+tx*4). EPI: 0=store(+bias), 1=add.
template <int EPI>
__global__ void __launch_bounds__(256, 2) gemm_f2(
    const float* __restrict__ A, const float* __restrict__ W,
    const float* __restrict__ bias, float* __restrict__ C,
    int M, int N, int K)
{
    constexpr int BM = 128, BN = 128, BK = 16, LDW = BM + 4;
    __shared__ float As[BK][LDW];
    __shared__ float Ws[BK][LDW];
    const int tid = threadIdx.x;
    const int tx = tid & 15, ty = tid >> 4;
    const int bm = blockIdx.y * BM, bn = blockIdx.x * BN;
    const int lrow = tid >> 2, lk = (tid & 3) * 4;

    unsigned long long acc[4][8];
#pragma unroll
    for (int i = 0; i < 4; i++)
#pragma unroll
        for (int j = 0; j < 8; j++) acc[i][j] = 0ULL;

    const float* Ap0 = A + (size_t)(bm + lrow) * K + lk;
    const float* Ap1 = Ap0 + (size_t)64 * K;
    const float* Wp0 = W + (size_t)(bn + lrow) * K + lk;
    const float* Wp1 = W + (size_t)(bn + 64 + lrow) * K + lk;
    const bool wv0 = (bn + lrow) < N, wv1 = (bn + 64 + lrow) < N;
    const float4 z4 = make_float4(0.f, 0.f, 0.f, 0.f);

    // prefetch chunk 0
    float4 pa0 = *(const float4*)Ap0;
    float4 pa1 = *(const float4*)Ap1;
    float4 pw0 = wv0 ? *(const float4*)Wp0 : z4;
    float4 pw1 = wv1 ? *(const float4*)Wp1 : z4;

    for (int k0 = 0; k0 < K; k0 += BK) {
        As[lk + 0][lrow] = pa0.x; As[lk + 1][lrow] = pa0.y;
        As[lk + 2][lrow] = pa0.z; As[lk + 3][lrow] = pa0.w;
        As[lk + 0][64 + lrow] = pa1.x; As[lk + 1][64 + lrow] = pa1.y;
        As[lk + 2][64 + lrow] = pa1.z; As[lk + 3][64 + lrow] = pa1.w;
        Ws[lk + 0][lrow] = pw0.x; Ws[lk + 1][lrow] = pw0.y;
        Ws[lk + 2][lrow] = pw0.z; Ws[lk + 3][lrow] = pw0.w;
        Ws[lk + 0][64 + lrow] = pw1.x; Ws[lk + 1][64 + lrow] = pw1.y;
        Ws[lk + 2][64 + lrow] = pw1.z; Ws[lk + 3][64 + lrow] = pw1.w;
        __syncthreads();
        if (k0 + BK < K) {  // prefetch next chunk while computing
            pa0 = *(const float4*)(Ap0 + k0 + BK);
            pa1 = *(const float4*)(Ap1 + k0 + BK);
            pw0 = wv0 ? *(const float4*)(Wp0 + k0 + BK) : z4;
            pw1 = wv1 ? *(const float4*)(Wp1 + k0 + BK) : z4;
        }
#pragma unroll
        for (int kk = 0; kk < BK; kk++) {
            float4 a0 = *(const float4*)&As[kk][ty * 8];
            float4 a1 = *(const float4*)&As[kk][ty * 8 + 4];
            float4 b0 = *(const float4*)&Ws[kk][tx * 4];
            float4 b1 = *(const float4*)&Ws[kk][64 + tx * 4];
            unsigned long long ap[4], bp[8];
            ap[0] = pk2(a0.x, a0.y); ap[1] = pk2(a0.z, a0.w);
            ap[2] = pk2(a1.x, a1.y); ap[3] = pk2(a1.z, a1.w);
            bp[0] = pkdup(b0.x); bp[1] = pkdup(b0.y);
            bp[2] = pkdup(b0.z); bp[3] = pkdup(b0.w);
            bp[4] = pkdup(b1.x); bp[5] = pkdup(b1.y);
            bp[6] = pkdup(b1.z); bp[7] = pkdup(b1.w);
#pragma unroll
            for (int i = 0; i < 4; i++)
#pragma unroll
                for (int j = 0; j < 8; j++) fma2(acc[i][j], ap[i], bp[j]);
        }
        __syncthreads();
    }

    // epilogue
#pragma unroll
    for (int i = 0; i < 4; i++) {
        float lo[8], hi[8];
#pragma unroll
        for (int j = 0; j < 8; j++) upk2(acc[i][j], lo[j], hi[j]);
#pragma unroll
        for (int g = 0; g < 2; g++) {
            int c0 = bn + g * 64 + tx * 4;
#pragma unroll
            for (int h = 0; h < 2; h++) {
                int r = bm + ty * 8 + 2 * i + h;
                const float* vals = (h ? hi : lo) + g * 4;
                if (c0 + 3 < N) {
                    size_t idx = (size_t)r * N + c0;
                    float4 v = make_float4(vals[0], vals[1], vals[2], vals[3]);
                    if (bias) {
                        float4 bb = *(const float4*)&bias[c0];
                        v.x += bb.x; v.y += bb.y; v.z += bb.z; v.w += bb.w;
                    }
                    if (EPI == 1) {
                        float4 o = *(const float4*)&C[idx];
                        v.x += o.x; v.y += o.y; v.z += o.z; v.w += o.w;
                    }
                    *(float4*)&C[idx] = v;
                } else {
#pragma unroll
                    for (int k = 0; k < 4; k++) {
                        int c = c0 + k;
                        if (c < N) {
                            size_t idx = (size_t)r * N + c;
                            float v = vals[k];
                            if (bias) v += bias[c];
                            if (EPI == 1) v += C[idx];
                            C[idx] = v;
                        }
                    }
                }
            }
        }
    }
}

// ---------------- RMSNorm (one row per 128-thread block) ----------------------
__global__ void rmsnorm_kernel(const float* __restrict__ x, const float* __restrict__ w,
                               float* __restrict__ out)
{
    int m = blockIdx.x;
    int tid = threadIdx.x;  // 128
    float v = x[(size_t)m * DM + tid];
    float s = v * v;
#pragma unroll
    for (int o = 16; o; o >>= 1) s += __shfl_xor_sync(0xffffffffu, s, o);
    __shared__ float red[4];
    if ((tid & 31) == 0) red[tid >> 5] = s;
    __syncthreads();
    float tot = red[0] + red[1] + red[2] + red[3];
    out[(size_t)m * DM + tid] = v * rsqrtf(tot * (1.f / DM) + 1e-5f) * w[tid];
}

// ---------------- depthwise causal conv (k=4) + silu, 4 steps/thread ----------
__global__ void conv_kernel(const float* __restrict__ xz, const float* __restrict__ cw,
                            const float* __restrict__ cb, float* __restrict__ out)
{
    int idx = blockIdx.x * blockDim.x + threadIdx.x;  // MTOT*DI/4
    int e = idx & (DI - 1);
    int mq = idx >> 8;
    int sq = mq & (S / 4 - 1);
    int b = mq >> 8;
    int m0 = b * S + sq * 4;
    const float* xp = xz + (size_t)m0 * (2 * DI) + e;
    float xv[7];
#pragma unroll
    for (int j = 0; j < 3; j++) xv[j] = (sq == 0) ? 0.f : xp[(j - 3) * (2 * DI)];
#pragma unroll
    for (int j = 3; j < 7; j++) xv[j] = xp[(j - 3) * (2 * DI)];
    float w0 = cw[e * 4 + 0], w1 = cw[e * 4 + 1], w2 = cw[e * 4 + 2], w3 = cw[e * 4 + 3];
    float b0 = cb[e];
    float* op = out + (size_t)m0 * DI + e;
#pragma unroll
    for (int j = 0; j < 4; j++) {
        float a = b0;
        a = fmaf(w0, xv[j], a);
        a = fmaf(w1, xv[j + 1], a);
        a = fmaf(w2, xv[j + 2], a);
        a = fmaf(w3, xv[j + 3], a);
        op[j * DI] = siluf(a);
    }
}

// ---------------- dt_proj (K=8) + softplus ------------------------------------
__global__ void dtproj_kernel(const float* __restrict__ dbc, const float* __restrict__ dtw,
                              const float* __restrict__ dtb, float* __restrict__ delta)
{
    constexpr int ROWS = 16;
    int tid = threadIdx.x;  // 256 -> one output channel per thread
    int m0 = blockIdx.x * ROWS;
    float wr[DTR];
#pragma unroll
    for (int k = 0; k < DTR; k++) wr[k] = dtw[tid * DTR + k];
    float bias = dtb[tid];
    __shared__ float rv[ROWS][DTR];
    if (tid < ROWS * DTR)
        rv[tid >> 3][tid & 7] = dbc[(size_t)(m0 + (tid >> 3)) * 40 + (tid & 7)];
    __syncthreads();
#pragma unroll
    for (int r = 0; r < ROWS; r++) {
        float x = bias;
#pragma unroll
        for (int k = 0; k < DTR; k++) x = fmaf(wr[k], rv[r][k], x);
        float d = (x > 20.f) ? x : log1pf(__expf(x));
        delta[(size_t)(m0 + r) * DI + tid] = d;
    }
}

// ---------------- selective scan + fused gate ---------------------------------
__global__ void __launch_bounds__(256) scan_kernel(
    const float* __restrict__ delta, const float* __restrict__ dbc,
    const float* __restrict__ u, const float* __restrict__ xz,
    const float* __restrict__ A_log, const float* __restrict__ Dp,
    float* __restrict__ y)
{
    int b = blockIdx.y;
    int egrp = blockIdx.x;
    int warp = threadIdx.x >> 5;
    int lane = threadIdx.x & 31;
    int half = lane >> 4;
    int n = lane & 15;
    int e = egrp * 16 + warp * 2 + half;
    float a2 = -__expf(A_log[e * DS + n]) * 1.4426950408889634f;
    float dcoef = Dp[e];
    size_t base = (size_t)b * S;
    const float* dptr = delta + base * DI + e;
    const float* uptr = u + base * DI + e;
    const float* bptr = dbc + base * 40 + 8 + n;
    const float* zptr = xz + base * (2 * DI) + DI + e;
    float* yptr = y + base * DI + e;
    float h = 0.f;
    for (int t = 0; t < S; t += 4) {
        float dv[4], uv[4], Bv[4], Cv[4];
#pragma unroll
        for (int j = 0; j < 4; j++) {
            dv[j] = dptr[j * DI];
            uv[j] = uptr[j * DI];
            Bv[j] = bptr[j * 40];
            Cv[j] = bptr[j * 40 + 16];
        }
#pragma unroll
        for (int j = 0; j < 4; j++) {
            float dA = exp2f(dv[j] * a2);
            h = fmaf(dA, h, dv[j] * Bv[j] * uv[j]);
            float p = h * Cv[j];
            p += __shfl_xor_sync(0xffffffffu, p, 1);
            p += __shfl_xor_sync(0xffffffffu, p, 2);
            p += __shfl_xor_sync(0xffffffffu, p, 4);
            p += __shfl_xor_sync(0xffffffffu, p, 8);
            if (n == 0) {
                float z = zptr[j * 2 * DI];
                yptr[j * DI] = fmaf(dcoef, uv[j], p) * siluf(z);
            }
        }
        dptr += 4 * DI; uptr += 4 * DI; bptr += 4 * 40;
        zptr += 4 * 2 * DI; yptr += 4 * DI;
    }
}

// ---------------- final: rmsnorm(last token) @ cls ----------------------------
__global__ void final_kernel(const float* __restrict__ h, const float* __restrict__ w,
                             const float* __restrict__ clsw, const float* __restrict__ clsb,
                             float* __restrict__ out)
{
    int b = blockIdx.x;
    int tid = threadIdx.x;  // 128
    float v = h[((size_t)b * S + (S - 1)) * DM + tid];
    float s = v * v;
#pragma unroll
    for (int o = 16; o; o >>= 1) s += __shfl_xor_sync(0xffffffffu, s, o);
    __shared__ float red[4];
    __shared__ float sh[DM];
    if ((tid & 31) == 0) red[tid >> 5] = s;
    __syncthreads();
    float tot = red[0] + red[1] + red[2] + red[3];
    sh[tid] = v * rsqrtf(tot * (1.f / DM) + 1e-5f) * w[tid];
    __syncthreads();
    if (tid < 2) {
        float acc = clsb[tid];
        for (int d = 0; d < DM; d++) acc = fmaf(sh[d], clsw[tid * DM + d], acc);
        out[b * 2 + tid] = acc;
    }
}

// ---------------- launcher ----------------------------------------------------
extern "C" void kernel_launch(void* const* d_in, const int* in_sizes, int n_in,
                              void* d_out, int out_size)
{
    (void)in_sizes; (void)n_in; (void)out_size;
    const float* x    = (const float*)d_in[0];
    const float* ipw  = (const float*)d_in[1];
    const float* ipb  = (const float*)d_in[2];
    const float* inw  = (const float*)d_in[3];
    const float* cw   = (const float*)d_in[4];
    const float* cb   = (const float*)d_in[5];
    const float* xpw  = (const float*)d_in[6];
    const float* dtw  = (const float*)d_in[7];
    const float* dtb  = (const float*)d_in[8];
    const float* alog = (const float*)d_in[9];
    const float* dvec = (const float*)d_in[10];
    const float* opw  = (const float*)d_in[11];
    const float* nw   = (const float*)d_in[12];
    const float* nfw  = (const float*)d_in[13];
    const float* clw  = (const float*)d_in[14];
    const float* clb  = (const float*)d_in[15];
    float* out = (float*)d_out;

    float *ph, *phn, *pxz, *pxc, *pdbc, *pdelta, *py;
    cudaGetSymbolAddress((void**)&ph, g_h);
    cudaGetSymbolAddress((void**)&phn, g_hn);
    cudaGetSymbolAddress((void**)&pxz, g_xz);
    cudaGetSymbolAddress((void**)&pxc, g_xc);
    cudaGetSymbolAddress((void**)&pdbc, g_dbc);
    cudaGetSymbolAddress((void**)&pdelta, g_delta);
    cudaGetSymbolAddress((void**)&py, g_y);

    // input proj: (MTOT x 64) @ (128 x 64)^T + b -> g_h
    gemm_f2<0><<<dim3(1, MTOT / 128), 256>>>(x, ipw, ipb, ph, MTOT, DM, 64);

    for (int i = 0; i < NL; i++) {
        rmsnorm_kernel<<<MTOT, 128>>>(ph, nw + i * DM, phn);
        gemm_f2<0><<<dim3(4, MTOT / 128), 256>>>(
            phn, inw + (size_t)i * 2 * DI * DM, nullptr, pxz, MTOT, 2 * DI, DM);
        conv_kernel<<<MTOT * DI / 4 / 256, 256>>>(pxz, cw + i * DI * 4, cb + i * DI, pxc);
        gemm_f2<0><<<dim3(1, MTOT / 128), 256>>>(
            pxc, xpw + (size_t)i * 40 * DI, nullptr, pdbc, MTOT, 40, DI);
        dtproj_kernel<<<MTOT / 16, 256>>>(pdbc, dtw + i * DI * DTR, dtb + i * DI, pdelta);
        scan_kernel<<<dim3(DI / 16, B), 256>>>(pdelta, pdbc, pxc, pxz,
                                               alog + i * DI * DS, dvec + i * DI, py);
        gemm_f2<1><<<dim3(1, MTOT / 128), 256>>>(
            py, opw + (size_t)i * DM * DI, nullptr, ph, MTOT, DM, DI);
    }

    final_kernel<<<B, 128>>>(ph, nfw, clw, clb, out);
}